// round 1
// baseline (speedup 1.0000x reference)
#include <cuda_runtime.h>
#include <cstdint>
#include <cstring>
#include <math.h>

// Problem dims
#define B_SZ     16384
#define T_SZ     10
#define H_SZ     256
#define G_SZ     1024      // 4*H
#define IN_RAW   39
#define IN_PAD   40
#define N_LABELS 500
#define ROWS     (B_SZ * T_SZ)   // 163840

typedef unsigned long long u64;

// ---------------- scratch (device globals; no allocation allowed) -------------
__device__ float g_x    [(size_t)ROWS * IN_PAD];   // gathered/padded input  [163840,40]
__device__ float g_xg   [(size_t)ROWS * G_SZ];     // input projections      [163840,1024]
__device__ float g_h1   [(size_t)ROWS * H_SZ];     // layer0 outputs         [163840,256]
__device__ float g_gates[(size_t)B_SZ * G_SZ];     // per-step gates         [16384,1024]
__device__ float g_h    [(size_t)B_SZ * H_SZ];
__device__ float g_c    [(size_t)B_SZ * H_SZ];
__device__ float g_wih0p[G_SZ * IN_PAD];           // Wih0 padded to K=40
__device__ float g_bias0[G_SZ];                    // bih0+bhh0
__device__ float g_bias1[G_SZ];                    // bih1+bhh1

// ---------------- small prep: pad Wih0, combine biases ------------------------
__global__ void prep_kernel(const float* __restrict__ Wih0,
                            const float* __restrict__ bih0, const float* __restrict__ bhh0,
                            const float* __restrict__ bih1, const float* __restrict__ bhh1)
{
    int i = blockIdx.x * blockDim.x + threadIdx.x;
    if (i < G_SZ) {
        g_bias0[i] = bih0[i] + bhh0[i];
        g_bias1[i] = bih1[i] + bhh1[i];
    }
    if (i < G_SZ * IN_PAD) {
        int n = i / IN_PAD, k = i % IN_PAD;
        g_wih0p[i] = (k < IN_RAW) ? Wih0[n * IN_RAW + k] : 0.f;
    }
}

// ---------------- embedding gather -> padded X [ROWS, 40] ---------------------
__global__ void gather_kernel(const int* __restrict__ car, const int* __restrict__ reg,
                              const int* __restrict__ poi, const int* __restrict__ week,
                              const int* __restrict__ timei,
                              const float* __restrict__ car_e, const float* __restrict__ reg_e,
                              const float* __restrict__ poi_e, const float* __restrict__ week_e,
                              const float* __restrict__ time_e)
{
    int i = blockIdx.x * blockDim.x + threadIdx.x;
    if (i >= ROWS * IN_PAD) return;
    int r = i / IN_PAD, j = i % IN_PAD;
    float v;
    if      (j < 16) v = car_e [(size_t)car  [r] * 16 + j];
    else if (j < 24) v = reg_e [(size_t)reg  [r] * 8  + (j - 16)];
    else if (j < 28) v = poi_e [(size_t)poi  [r] * 4  + (j - 24)];
    else if (j < 31) v = week_e[(size_t)week [r] * 3  + (j - 28)];
    else if (j < 39) v = time_e[(size_t)timei[r] * 8  + (j - 31)];
    else             v = 0.f;
    g_x[i] = v;
}

// ---------------- SGEMM  C[M,N] = A[M,K] @ W[N,K]^T (+bias) (+row-addend) -----
// f32x2 packed-FMA microkernel: 128x128 tile, BK=8, 256 threads, 8x8 per thread
// (accumulators held as 32 x f32x2 pairs over adjacent N columns).
#define BM 128
#define BN 128
#define BKK 8

__device__ __forceinline__ u64 pack2(float x) {
    u64 r; asm("mov.b64 %0, {%1, %1};" : "=l"(r) : "f"(x)); return r;
}
__device__ __forceinline__ void fma2(u64& d, u64 a, u64 b) {
    asm("fma.rn.f32x2 %0, %1, %2, %3;" : "=l"(d) : "l"(a), "l"(b), "l"(d));
}

__global__ __launch_bounds__(256, 2)
void sgemm_tn(const float* __restrict__ A, int lda,
              const float* __restrict__ W,              // [N,K] row-major, stride K
              const float* __restrict__ bias,           // [N] or null
              const float* __restrict__ Add, long addStride, // [M,*] row-addend or null
              float* __restrict__ C, int ldc,
              int M, int N, int K)
{
    __shared__ __align__(16) float As[BKK][BM];
    __shared__ __align__(16) float Bs[BKK][BN];

    const int m0 = blockIdx.y * BM;
    const int n0 = blockIdx.x * BN;
    const int tid = threadIdx.x;
    const int ty = tid >> 4;        // 0..15 -> 8-row group
    const int tx = tid & 15;        // 0..15 -> 8-col group

    u64 acc[8][4];
#pragma unroll
    for (int i = 0; i < 8; i++)
#pragma unroll
        for (int j = 0; j < 4; j++) acc[i][j] = 0ull;

    const int lrow = tid >> 1;        // 0..127
    const int lk   = (tid & 1) * 4;   // 0 or 4

    for (int k0 = 0; k0 < K; k0 += BKK) {
        // A tile: 128 rows x 8 k  (one float4 per thread, transposed store)
        float4 av = *reinterpret_cast<const float4*>(&A[(size_t)(m0 + lrow) * lda + k0 + lk]);
        As[lk + 0][lrow] = av.x; As[lk + 1][lrow] = av.y;
        As[lk + 2][lrow] = av.z; As[lk + 3][lrow] = av.w;
        // W tile: 128 n-rows x 8 k
        int nr = n0 + lrow;
        float4 bv = make_float4(0.f, 0.f, 0.f, 0.f);
        if (nr < N) bv = *reinterpret_cast<const float4*>(&W[(size_t)nr * K + k0 + lk]);
        Bs[lk + 0][lrow] = bv.x; Bs[lk + 1][lrow] = bv.y;
        Bs[lk + 2][lrow] = bv.z; Bs[lk + 3][lrow] = bv.w;
        __syncthreads();

#pragma unroll
        for (int kk = 0; kk < BKK; ++kk) {
            float a[8];
            *reinterpret_cast<float4*>(&a[0]) = *reinterpret_cast<const float4*>(&As[kk][ty * 8]);
            *reinterpret_cast<float4*>(&a[4]) = *reinterpret_cast<const float4*>(&As[kk][ty * 8 + 4]);
            u64 b[4];
#pragma unroll
            for (int j = 0; j < 4; j++)
                b[j] = *reinterpret_cast<const u64*>(&Bs[kk][tx * 8 + 2 * j]);
#pragma unroll
            for (int i = 0; i < 8; i++) {
                u64 aa = pack2(a[i]);
#pragma unroll
                for (int j = 0; j < 4; j++) fma2(acc[i][j], aa, b[j]);
            }
        }
        __syncthreads();
    }

    // epilogue (N is always even here: 1024 or 500; n even => n<N implies n+1<N)
#pragma unroll
    for (int i = 0; i < 8; i++) {
        size_t m = (size_t)(m0 + ty * 8 + i);
        const float* addrow = Add ? (Add + m * addStride) : nullptr;
        float* crow = C + m * ldc;
#pragma unroll
        for (int j = 0; j < 4; j++) {
            int n = n0 + tx * 8 + 2 * j;
            if (n < N) {
                union { u64 u; float2 f; } cv; cv.u = acc[i][j];
                float vx = cv.f.x, vy = cv.f.y;
                if (bias)   { vx += bias[n];   vy += bias[n + 1]; }
                if (addrow) { vx += addrow[n]; vy += addrow[n + 1]; }
                crow[n]     = vx;
                crow[n + 1] = vy;
            }
        }
    }
}

// ---------------- pointwise LSTM cell update ----------------------------------
__global__ void lstm_pointwise(const float* __restrict__ gates, long gstride,
                               float* __restrict__ h, float* __restrict__ c,
                               float* __restrict__ h1out, int t, int czero)
{
    int idx = blockIdx.x * blockDim.x + threadIdx.x;
    if (idx >= B_SZ * H_SZ) return;
    int b = idx >> 8, j = idx & 255;
    const float* row = gates + (size_t)b * gstride;
    float iv = row[j];
    float fv = row[256 + j];
    float gv = row[512 + j];
    float ov = row[768 + j];
    iv = 1.f / (1.f + expf(-iv));
    fv = 1.f / (1.f + expf(-fv));
    ov = 1.f / (1.f + expf(-ov));
    gv = tanhf(gv);
    float cold = czero ? 0.f : c[idx];
    float cn = fv * cold + iv * gv;
    float hn = ov * tanhf(cn);
    c[idx] = cn;
    h[idx] = hn;
    if (h1out) h1out[((size_t)b * T_SZ + t) * H_SZ + j] = hn;
}

// ---------------- launch ------------------------------------------------------
extern "C" void kernel_launch(void* const* d_in, const int* in_sizes, int n_in,
                              void* d_out, int out_size)
{
    const int*   car    = (const int*)  d_in[0];
    const int*   reg    = (const int*)  d_in[1];
    const int*   poi    = (const int*)  d_in[2];
    const int*   week   = (const int*)  d_in[3];
    const int*   timei  = (const int*)  d_in[4];
    const float* car_e  = (const float*)d_in[5];
    const float* reg_e  = (const float*)d_in[6];
    const float* poi_e  = (const float*)d_in[7];
    const float* week_e = (const float*)d_in[8];
    const float* time_e = (const float*)d_in[9];
    const float* Wih0   = (const float*)d_in[10];
    const float* Whh0   = (const float*)d_in[11];
    const float* bih0   = (const float*)d_in[12];
    const float* bhh0   = (const float*)d_in[13];
    const float* Wih1   = (const float*)d_in[14];
    const float* Whh1   = (const float*)d_in[15];
    const float* bih1   = (const float*)d_in[16];
    const float* bhh1   = (const float*)d_in[17];
    const float* Wout   = (const float*)d_in[18];
    const float* bout   = (const float*)d_in[19];
    float* out = (float*)d_out;

    float *xp, *xg, *h1, *gates, *h, *c, *wih0p, *bias0, *bias1;
    cudaGetSymbolAddress((void**)&xp,    g_x);
    cudaGetSymbolAddress((void**)&xg,    g_xg);
    cudaGetSymbolAddress((void**)&h1,    g_h1);
    cudaGetSymbolAddress((void**)&gates, g_gates);
    cudaGetSymbolAddress((void**)&h,     g_h);
    cudaGetSymbolAddress((void**)&c,     g_c);
    cudaGetSymbolAddress((void**)&wih0p, g_wih0p);
    cudaGetSymbolAddress((void**)&bias0, g_bias0);
    cudaGetSymbolAddress((void**)&bias1, g_bias1);

    const dim3 blk(256);
    const long XGSTRIDE = (long)T_SZ * G_SZ;   // 10240

    prep_kernel<<<(G_SZ * IN_PAD + 255) / 256, 256>>>(Wih0, bih0, bhh0, bih1, bhh1);
    gather_kernel<<<(ROWS * IN_PAD + 255) / 256, 256>>>(
        car, reg, poi, week, timei, car_e, reg_e, poi_e, week_e, time_e);

    // layer0 input projection: xg = X @ Wih0p^T + (bih0+bhh0)   [163840,1024]
    sgemm_tn<<<dim3(G_SZ / BN, ROWS / BM), blk>>>(
        xp, IN_PAD, wih0p, bias0, nullptr, 0, xg, G_SZ, ROWS, G_SZ, IN_PAD);

    // layer0 recurrence
    for (int t = 0; t < T_SZ; ++t) {
        const float* gsrc; long gstride;
        if (t == 0) { gsrc = xg; gstride = XGSTRIDE; }      // h0 = 0 -> gates = xg_t
        else {
            sgemm_tn<<<dim3(G_SZ / BN, B_SZ / BM), blk>>>(
                h, H_SZ, Whh0, nullptr, xg + (size_t)t * G_SZ, XGSTRIDE,
                gates, G_SZ, B_SZ, G_SZ, H_SZ);
            gsrc = gates; gstride = G_SZ;
        }
        lstm_pointwise<<<(B_SZ * H_SZ) / 256, 256>>>(gsrc, gstride, h, c, h1, t, t == 0);
    }

    // layer1 input projection: xg = H1 @ Wih1^T + (bih1+bhh1)   [163840,1024]
    sgemm_tn<<<dim3(G_SZ / BN, ROWS / BM), blk>>>(
        h1, H_SZ, Wih1, bias1, nullptr, 0, xg, G_SZ, ROWS, G_SZ, H_SZ);

    // layer1 recurrence
    for (int t = 0; t < T_SZ; ++t) {
        const float* gsrc; long gstride;
        if (t == 0) { gsrc = xg; gstride = XGSTRIDE; }
        else {
            sgemm_tn<<<dim3(G_SZ / BN, B_SZ / BM), blk>>>(
                h, H_SZ, Whh1, nullptr, xg + (size_t)t * G_SZ, XGSTRIDE,
                gates, G_SZ, B_SZ, G_SZ, H_SZ);
            gsrc = gates; gstride = G_SZ;
        }
        lstm_pointwise<<<(B_SZ * H_SZ) / 256, 256>>>(gsrc, gstride, h, c, nullptr, t, t == 0);
    }

    // output head: out = h_last @ Wout^T + bout   [16384,500]
    sgemm_tn<<<dim3((N_LABELS + BN - 1) / BN, B_SZ / BM), blk>>>(
        h, H_SZ, Wout, bout, nullptr, 0, out, N_LABELS, B_SZ, N_LABELS, H_SZ);
}

// round 2
// speedup vs baseline: 1.0000x; 1.0000x over previous
#include <cuda_runtime.h>
#include <cstdint>
#include <cstring>
#include <math.h>

// Problem dims
#define B_SZ     16384
#define T_SZ     10
#define H_SZ     256
#define G_SZ     1024      // 4*H
#define IN_RAW   39
#define IN_PAD   40
#define N_LABELS 500
#define ROWS     (B_SZ * T_SZ)   // 163840

typedef unsigned long long u64;

// ---------------- scratch (device globals; no allocation allowed) -------------
__device__ float g_x    [(size_t)ROWS * IN_PAD];   // gathered/padded input  [163840,40]
__device__ float g_xg   [(size_t)ROWS * G_SZ];     // input projections      [163840,1024]
__device__ float g_h1   [(size_t)ROWS * H_SZ];     // layer0 outputs         [163840,256]
__device__ float g_gates[(size_t)B_SZ * G_SZ];     // per-step gates         [16384,1024]
__device__ float g_h    [(size_t)B_SZ * H_SZ];
__device__ float g_c    [(size_t)B_SZ * H_SZ];
__device__ float g_wih0p[G_SZ * IN_PAD];           // Wih0 padded to K=40
__device__ float g_bias0[G_SZ];                    // bih0+bhh0
__device__ float g_bias1[G_SZ];                    // bih1+bhh1

// ---------------- small prep: pad Wih0, combine biases ------------------------
__global__ void prep_kernel(const float* __restrict__ Wih0,
                            const float* __restrict__ bih0, const float* __restrict__ bhh0,
                            const float* __restrict__ bih1, const float* __restrict__ bhh1)
{
    int i = blockIdx.x * blockDim.x + threadIdx.x;
    if (i < G_SZ) {
        g_bias0[i] = bih0[i] + bhh0[i];
        g_bias1[i] = bih1[i] + bhh1[i];
    }
    if (i < G_SZ * IN_PAD) {
        int n = i / IN_PAD, k = i % IN_PAD;
        g_wih0p[i] = (k < IN_RAW) ? Wih0[n * IN_RAW + k] : 0.f;
    }
}

// ---------------- embedding gather -> padded X [ROWS, 40] ---------------------
__global__ void gather_kernel(const int* __restrict__ car, const int* __restrict__ reg,
                              const int* __restrict__ poi, const int* __restrict__ week,
                              const int* __restrict__ timei,
                              const float* __restrict__ car_e, const float* __restrict__ reg_e,
                              const float* __restrict__ poi_e, const float* __restrict__ week_e,
                              const float* __restrict__ time_e)
{
    int i = blockIdx.x * blockDim.x + threadIdx.x;
    if (i >= ROWS * IN_PAD) return;
    int r = i / IN_PAD, j = i % IN_PAD;
    float v;
    if      (j < 16) v = car_e [(size_t)car  [r] * 16 + j];
    else if (j < 24) v = reg_e [(size_t)reg  [r] * 8  + (j - 16)];
    else if (j < 28) v = poi_e [(size_t)poi  [r] * 4  + (j - 24)];
    else if (j < 31) v = week_e[(size_t)week [r] * 3  + (j - 28)];
    else if (j < 39) v = time_e[(size_t)timei[r] * 8  + (j - 31)];
    else             v = 0.f;
    g_x[i] = v;
}

// ---------------- SGEMM  C[M,N] = A[M,K] @ W[N,K]^T (+bias) (+row-addend) -----
// f32x2 packed-FMA microkernel: 128x128 tile, BK=8, 256 threads, 8x8 per thread
// (accumulators held as 32 x f32x2 pairs over adjacent N columns).
#define BM 128
#define BN 128
#define BKK 8

__device__ __forceinline__ u64 pack2(float x) {
    u64 r; asm("mov.b64 %0, {%1, %1};" : "=l"(r) : "f"(x)); return r;
}
__device__ __forceinline__ void fma2(u64& d, u64 a, u64 b) {
    asm("fma.rn.f32x2 %0, %1, %2, %3;" : "=l"(d) : "l"(a), "l"(b), "l"(d));
}

__global__ __launch_bounds__(256, 2)
void sgemm_tn(const float* __restrict__ A, int lda,
              const float* __restrict__ W,              // [N,K] row-major, stride K
              const float* __restrict__ bias,           // [N] or null
              const float* __restrict__ Add, long addStride, // [M,*] row-addend or null
              float* __restrict__ C, int ldc,
              int M, int N, int K)
{
    __shared__ __align__(16) float As[BKK][BM];
    __shared__ __align__(16) float Bs[BKK][BN];

    const int m0 = blockIdx.y * BM;
    const int n0 = blockIdx.x * BN;
    const int tid = threadIdx.x;
    const int ty = tid >> 4;        // 0..15 -> 8-row group
    const int tx = tid & 15;        // 0..15 -> 8-col group

    u64 acc[8][4];
#pragma unroll
    for (int i = 0; i < 8; i++)
#pragma unroll
        for (int j = 0; j < 4; j++) acc[i][j] = 0ull;

    const int lrow = tid >> 1;        // 0..127
    const int lk   = (tid & 1) * 4;   // 0 or 4

    for (int k0 = 0; k0 < K; k0 += BKK) {
        // A tile: 128 rows x 8 k  (one float4 per thread, transposed store)
        float4 av = *reinterpret_cast<const float4*>(&A[(size_t)(m0 + lrow) * lda + k0 + lk]);
        As[lk + 0][lrow] = av.x; As[lk + 1][lrow] = av.y;
        As[lk + 2][lrow] = av.z; As[lk + 3][lrow] = av.w;
        // W tile: 128 n-rows x 8 k
        int nr = n0 + lrow;
        float4 bv = make_float4(0.f, 0.f, 0.f, 0.f);
        if (nr < N) bv = *reinterpret_cast<const float4*>(&W[(size_t)nr * K + k0 + lk]);
        Bs[lk + 0][lrow] = bv.x; Bs[lk + 1][lrow] = bv.y;
        Bs[lk + 2][lrow] = bv.z; Bs[lk + 3][lrow] = bv.w;
        __syncthreads();

#pragma unroll
        for (int kk = 0; kk < BKK; ++kk) {
            float a[8];
            *reinterpret_cast<float4*>(&a[0]) = *reinterpret_cast<const float4*>(&As[kk][ty * 8]);
            *reinterpret_cast<float4*>(&a[4]) = *reinterpret_cast<const float4*>(&As[kk][ty * 8 + 4]);
            u64 b[4];
#pragma unroll
            for (int j = 0; j < 4; j++)
                b[j] = *reinterpret_cast<const u64*>(&Bs[kk][tx * 8 + 2 * j]);
#pragma unroll
            for (int i = 0; i < 8; i++) {
                u64 aa = pack2(a[i]);
#pragma unroll
                for (int j = 0; j < 4; j++) fma2(acc[i][j], aa, b[j]);
            }
        }
        __syncthreads();
    }

    // epilogue (N is always even here: 1024 or 500; n even => n<N implies n+1<N)
#pragma unroll
    for (int i = 0; i < 8; i++) {
        size_t m = (size_t)(m0 + ty * 8 + i);
        const float* addrow = Add ? (Add + m * addStride) : nullptr;
        float* crow = C + m * ldc;
#pragma unroll
        for (int j = 0; j < 4; j++) {
            int n = n0 + tx * 8 + 2 * j;
            if (n < N) {
                union { u64 u; float2 f; } cv; cv.u = acc[i][j];
                float vx = cv.f.x, vy = cv.f.y;
                if (bias)   { vx += bias[n];   vy += bias[n + 1]; }
                if (addrow) { vx += addrow[n]; vy += addrow[n + 1]; }
                crow[n]     = vx;
                crow[n + 1] = vy;
            }
        }
    }
}

// ---------------- pointwise LSTM cell update ----------------------------------
__global__ void lstm_pointwise(const float* __restrict__ gates, long gstride,
                               float* __restrict__ h, float* __restrict__ c,
                               float* __restrict__ h1out, int t, int czero)
{
    int idx = blockIdx.x * blockDim.x + threadIdx.x;
    if (idx >= B_SZ * H_SZ) return;
    int b = idx >> 8, j = idx & 255;
    const float* row = gates + (size_t)b * gstride;
    float iv = row[j];
    float fv = row[256 + j];
    float gv = row[512 + j];
    float ov = row[768 + j];
    iv = 1.f / (1.f + expf(-iv));
    fv = 1.f / (1.f + expf(-fv));
    ov = 1.f / (1.f + expf(-ov));
    gv = tanhf(gv);
    float cold = czero ? 0.f : c[idx];
    float cn = fv * cold + iv * gv;
    float hn = ov * tanhf(cn);
    c[idx] = cn;
    h[idx] = hn;
    if (h1out) h1out[((size_t)b * T_SZ + t) * H_SZ + j] = hn;
}

// ---------------- launch ------------------------------------------------------
extern "C" void kernel_launch(void* const* d_in, const int* in_sizes, int n_in,
                              void* d_out, int out_size)
{
    const int*   car    = (const int*)  d_in[0];
    const int*   reg    = (const int*)  d_in[1];
    const int*   poi    = (const int*)  d_in[2];
    const int*   week   = (const int*)  d_in[3];
    const int*   timei  = (const int*)  d_in[4];
    const float* car_e  = (const float*)d_in[5];
    const float* reg_e  = (const float*)d_in[6];
    const float* poi_e  = (const float*)d_in[7];
    const float* week_e = (const float*)d_in[8];
    const float* time_e = (const float*)d_in[9];
    const float* Wih0   = (const float*)d_in[10];
    const float* Whh0   = (const float*)d_in[11];
    const float* bih0   = (const float*)d_in[12];
    const float* bhh0   = (const float*)d_in[13];
    const float* Wih1   = (const float*)d_in[14];
    const float* Whh1   = (const float*)d_in[15];
    const float* bih1   = (const float*)d_in[16];
    const float* bhh1   = (const float*)d_in[17];
    const float* Wout   = (const float*)d_in[18];
    const float* bout   = (const float*)d_in[19];
    float* out = (float*)d_out;

    float *xp, *xg, *h1, *gates, *h, *c, *wih0p, *bias0, *bias1;
    cudaGetSymbolAddress((void**)&xp,    g_x);
    cudaGetSymbolAddress((void**)&xg,    g_xg);
    cudaGetSymbolAddress((void**)&h1,    g_h1);
    cudaGetSymbolAddress((void**)&gates, g_gates);
    cudaGetSymbolAddress((void**)&h,     g_h);
    cudaGetSymbolAddress((void**)&c,     g_c);
    cudaGetSymbolAddress((void**)&wih0p, g_wih0p);
    cudaGetSymbolAddress((void**)&bias0, g_bias0);
    cudaGetSymbolAddress((void**)&bias1, g_bias1);

    const dim3 blk(256);
    const long XGSTRIDE = (long)T_SZ * G_SZ;   // 10240

    prep_kernel<<<(G_SZ * IN_PAD + 255) / 256, 256>>>(Wih0, bih0, bhh0, bih1, bhh1);
    gather_kernel<<<(ROWS * IN_PAD + 255) / 256, 256>>>(
        car, reg, poi, week, timei, car_e, reg_e, poi_e, week_e, time_e);

    // layer0 input projection: xg = X @ Wih0p^T + (bih0+bhh0)   [163840,1024]
    sgemm_tn<<<dim3(G_SZ / BN, ROWS / BM), blk>>>(
        xp, IN_PAD, wih0p, bias0, nullptr, 0, xg, G_SZ, ROWS, G_SZ, IN_PAD);

    // layer0 recurrence
    for (int t = 0; t < T_SZ; ++t) {
        const float* gsrc; long gstride;
        if (t == 0) { gsrc = xg; gstride = XGSTRIDE; }      // h0 = 0 -> gates = xg_t
        else {
            sgemm_tn<<<dim3(G_SZ / BN, B_SZ / BM), blk>>>(
                h, H_SZ, Whh0, nullptr, xg + (size_t)t * G_SZ, XGSTRIDE,
                gates, G_SZ, B_SZ, G_SZ, H_SZ);
            gsrc = gates; gstride = G_SZ;
        }
        lstm_pointwise<<<(B_SZ * H_SZ) / 256, 256>>>(gsrc, gstride, h, c, h1, t, t == 0);
    }

    // layer1 input projection: xg = H1 @ Wih1^T + (bih1+bhh1)   [163840,1024]
    sgemm_tn<<<dim3(G_SZ / BN, ROWS / BM), blk>>>(
        h1, H_SZ, Wih1, bias1, nullptr, 0, xg, G_SZ, ROWS, G_SZ, H_SZ);

    // layer1 recurrence
    for (int t = 0; t < T_SZ; ++t) {
        const float* gsrc; long gstride;
        if (t == 0) { gsrc = xg; gstride = XGSTRIDE; }
        else {
            sgemm_tn<<<dim3(G_SZ / BN, B_SZ / BM), blk>>>(
                h, H_SZ, Whh1, nullptr, xg + (size_t)t * G_SZ, XGSTRIDE,
                gates, G_SZ, B_SZ, G_SZ, H_SZ);
            gsrc = gates; gstride = G_SZ;
        }
        lstm_pointwise<<<(B_SZ * H_SZ) / 256, 256>>>(gsrc, gstride, h, c, nullptr, t, t == 0);
    }

    // output head: out = h_last @ Wout^T + bout   [16384,500]
    sgemm_tn<<<dim3((N_LABELS + BN - 1) / BN, B_SZ / BM), blk>>>(
        h, H_SZ, Wout, bout, nullptr, 0, out, N_LABELS, B_SZ, N_LABELS, H_SZ);
}

// round 4
// speedup vs baseline: 1.9487x; 1.9486x over previous
#include <cuda_runtime.h>
#include <cuda_bf16.h>
#include <cstdint>
#include <math.h>

#define B_SZ     16384
#define T_SZ     10
#define H_SZ     256
#define G_SZ     1024
#define N_LABELS 500
#define ROWS     (B_SZ * T_SZ)     // 163840
#define XPAD     64

typedef unsigned long long u64;
typedef unsigned int u32;
typedef __nv_bfloat16 bf16;

// ---------------- device scratch (no allocations allowed) --------------------
__device__ bf16  g_xhi [(size_t)ROWS * XPAD];
__device__ bf16  g_xlo [(size_t)ROWS * XPAD];
__device__ float g_xg  [(size_t)ROWS * G_SZ];      // input projections (fp32)
__device__ bf16  g_h1hi[(size_t)ROWS * H_SZ];
__device__ bf16  g_h1lo[(size_t)ROWS * H_SZ];
__device__ float g_gates[(size_t)B_SZ * G_SZ];
__device__ bf16  g_hhi [(size_t)B_SZ * H_SZ];
__device__ bf16  g_hlo [(size_t)B_SZ * H_SZ];
__device__ float g_c   [(size_t)B_SZ * H_SZ];
__device__ float g_bias0[G_SZ];
__device__ float g_bias1[G_SZ];
// pre-split, pre-swizzled weight tile images: [tile*nkc + kc][256 rows][64 cols]
__device__ bf16 g_wih0_hi[ 4 * 1 * 16384], g_wih0_lo[ 4 * 1 * 16384];
__device__ bf16 g_whh0_hi[ 4 * 4 * 16384], g_whh0_lo[ 4 * 4 * 16384];
__device__ bf16 g_wih1_hi[ 4 * 4 * 16384], g_wih1_lo[ 4 * 4 * 16384];
__device__ bf16 g_whh1_hi[ 4 * 4 * 16384], g_whh1_lo[ 4 * 4 * 16384];
__device__ bf16 g_wout_hi[ 2 * 4 * 16384], g_wout_lo[ 2 * 4 * 16384];

// ---------------- PTX helpers ------------------------------------------------
__device__ __forceinline__ u32 smem_u32(const void* p) {
    u32 a; asm("{ .reg .u64 t; cvta.to.shared.u64 t, %1; cvt.u32.u64 %0, t; }"
               : "=r"(a) : "l"(p));
    return a;
}
__device__ __forceinline__ void cp16(u32 dst, const void* src) {
    asm volatile("cp.async.cg.shared.global [%0], [%1], 16;" :: "r"(dst), "l"(src));
}
__device__ __forceinline__ void cp_commit() { asm volatile("cp.async.commit_group;"); }
template <int N> __device__ __forceinline__ void cp_wait() {
    asm volatile("cp.async.wait_group %0;" :: "n"(N));
}
__device__ __forceinline__ void ldm4(u32& r0, u32& r1, u32& r2, u32& r3, u32 addr) {
    asm volatile("ldmatrix.sync.aligned.m8n8.x4.shared.b16 {%0,%1,%2,%3}, [%4];"
                 : "=r"(r0), "=r"(r1), "=r"(r2), "=r"(r3) : "r"(addr));
}
__device__ __forceinline__ void mma16(float* d, const u32* a, const u32* b) {
    asm volatile("mma.sync.aligned.m16n8k16.row.col.f32.bf16.bf16.f32 "
                 "{%0,%1,%2,%3}, {%4,%5,%6,%7}, {%8,%9}, {%0,%1,%2,%3};"
                 : "+f"(d[0]), "+f"(d[1]), "+f"(d[2]), "+f"(d[3])
                 : "r"(a[0]), "r"(a[1]), "r"(a[2]), "r"(a[3]), "r"(b[0]), "r"(b[1]));
}

// ---------------- prep kernels ----------------------------------------------
__global__ void prep_bias(const float* bih0, const float* bhh0,
                          const float* bih1, const float* bhh1) {
    int i = blockIdx.x * blockDim.x + threadIdx.x;
    if (i < G_SZ) { g_bias0[i] = bih0[i] + bhh0[i]; g_bias1[i] = bih1[i] + bhh1[i]; }
}

// split W[Nrows, Kw] into hi/lo swizzled tile images
__global__ void prep_wsplit(const float* __restrict__ W, int Kw, int Nrows,
                            int nkc, long total, bf16* __restrict__ hi, bf16* __restrict__ lo) {
    long id = (long)blockIdx.x * blockDim.x + threadIdx.x;
    if (id >= total) return;
    int c  = (int)(id & 63);
    int r  = (int)((id >> 6) & 255);
    long tc = id >> 14;
    int kc = (int)(tc % nkc), nt = (int)(tc / nkc);
    int n = nt * 256 + r, k = kc * 64 + c;
    float v = (n < Nrows && k < Kw) ? W[(size_t)n * Kw + k] : 0.f;
    bf16 h = __float2bfloat16(v);
    size_t pos = ((size_t)tc * 256 + r) * 64 + (size_t)((((c >> 3) ^ (r & 7)) << 3) | (c & 7));
    hi[pos] = h;
    lo[pos] = __float2bfloat16(v - __bfloat162float(h));
}

// embedding gather -> split-bf16 X [ROWS, 64]
__global__ void gather_kernel(const int* __restrict__ car, const int* __restrict__ reg,
                              const int* __restrict__ poi, const int* __restrict__ week,
                              const int* __restrict__ timei,
                              const float* __restrict__ ce, const float* __restrict__ re,
                              const float* __restrict__ pe, const float* __restrict__ we,
                              const float* __restrict__ te) {
    long i = (long)blockIdx.x * blockDim.x + threadIdx.x;
    if (i >= (long)ROWS * XPAD) return;
    long r = i / XPAD; int j = (int)(i % XPAD);
    float v = 0.f;
    if      (j < 16) v = ce[(size_t)car  [r] * 16 + j];
    else if (j < 24) v = re[(size_t)reg  [r] * 8  + (j - 16)];
    else if (j < 28) v = pe[(size_t)poi  [r] * 4  + (j - 24)];
    else if (j < 31) v = we[(size_t)week [r] * 3  + (j - 28)];
    else if (j < 39) v = te[(size_t)timei[r] * 8  + (j - 31)];
    bf16 h = __float2bfloat16(v);
    g_xhi[i] = h;
    g_xlo[i] = __float2bfloat16(v - __bfloat162float(h));
}

// ---------------- split-bf16 mma.sync GEMM  C = A @ W^T (+bias)(+addend) -----
// BM=128, BN=128, BK=64; 256 threads, 8 warps as 2x4 (warp tile 64x32);
// 3 passes per k16: Ahi*Bhi + Alo*Bhi + Ahi*Blo.
#define STG_BYTES 65536
#define SM_BYTES  (2 * STG_BYTES)   // 131072

__global__ void __launch_bounds__(256)
gemm_mma(const bf16* __restrict__ Ahi, const bf16* __restrict__ Alo, int lda,
         const bf16* __restrict__ Whi, const bf16* __restrict__ Wlo, int nkc,
         const float* __restrict__ bias,
         const float* __restrict__ Add, long addStride,
         float* __restrict__ C, int ldc, int Nvalid)
{
    extern __shared__ __align__(1024) char sm[];
    const u32 sb = smem_u32(sm);

    const int tid = threadIdx.x, wid = tid >> 5, lid = tid & 31;
    const int m0 = blockIdx.y * 128;
    const int n0 = blockIdx.x * 128;
    const int tile = n0 >> 8, rowbase = n0 & 255;
    const int m_w = (wid >> 2) * 64, n_w = (wid & 2 ? 64 : 0) + (wid & 1) * 32;

    float acc[4][4][4];
#pragma unroll
    for (int a = 0; a < 4; a++)
#pragma unroll
        for (int b = 0; b < 4; b++)
#pragma unroll
            for (int e = 0; e < 4; e++) acc[a][b][e] = 0.f;

    const int au = tid & 7, ar = tid >> 3;

    auto load_stage = [&](int s, int kc) {
        u32 base = sb + s * STG_BYTES;
        const size_t acol = (size_t)kc * 64 + au * 8;
#pragma unroll
        for (int i = 0; i < 4; i++) {
            int r = ar + i * 32;
            u32 d = base + ((r * 64 + ((au ^ (r & 7)) << 3)) << 1);
            const size_t go = (size_t)(m0 + r) * lda + acol;
            cp16(d,         Ahi + go);
            cp16(d + 16384, Alo + go);
        }
        const size_t ib = (size_t)(tile * nkc + kc) * 16384 + (size_t)rowbase * 64;
#pragma unroll
        for (int i = 0; i < 4; i++) {
            int j = tid + i * 256;
            cp16(base + 32768 + j * 16, Whi + ib + (size_t)j * 8);
            cp16(base + 49152 + j * 16, Wlo + ib + (size_t)j * 8);
        }
        cp_commit();
    };

    const int lrow = lid & 15, lk = lid >> 4;

    load_stage(0, 0);
    for (int kc = 0; kc < nkc; ++kc) {
        if (kc + 1 < nkc) { load_stage((kc + 1) & 1, kc + 1); cp_wait<1>(); }
        else              { cp_wait<0>(); }
        __syncthreads();

        const u32 aBase = sb + (kc & 1) * STG_BYTES;
        const u32 bBase = aBase + 32768;

#pragma unroll
        for (int k16 = 0; k16 < 4; ++k16) {
            const int kb8 = k16 * 2 + lk;
            u32 bh[4][2], bl[4][2];
#pragma unroll
            for (int blk = 0; blk < 2; ++blk) {
                int row = n_w + blk * 16 + lrow;
                u32 ad = bBase + ((row * 64 + ((kb8 ^ (row & 7)) << 3)) << 1);
                u32 r0, r1, r2, r3;
                ldm4(r0, r1, r2, r3, ad);
                bh[blk * 2][0] = r0; bh[blk * 2][1] = r2;
                bh[blk * 2 + 1][0] = r1; bh[blk * 2 + 1][1] = r3;
                ldm4(r0, r1, r2, r3, ad + 16384);
                bl[blk * 2][0] = r0; bl[blk * 2][1] = r2;
                bl[blk * 2 + 1][0] = r1; bl[blk * 2 + 1][1] = r3;
            }
#pragma unroll
            for (int mt = 0; mt < 4; ++mt) {
                int row = m_w + mt * 16 + lrow;
                u32 ad = aBase + ((row * 64 + ((kb8 ^ (row & 7)) << 3)) << 1);
                u32 ah[4], al[4];
                ldm4(ah[0], ah[1], ah[2], ah[3], ad);
                ldm4(al[0], al[1], al[2], al[3], ad + 16384);
#pragma unroll
                for (int nt = 0; nt < 4; ++nt) mma16(acc[mt][nt], ah, bh[nt]);
#pragma unroll
                for (int nt = 0; nt < 4; ++nt) mma16(acc[mt][nt], al, bh[nt]);
#pragma unroll
                for (int nt = 0; nt < 4; ++nt) mma16(acc[mt][nt], ah, bl[nt]);
            }
        }
        __syncthreads();
    }

    // epilogue
#pragma unroll
    for (int mt = 0; mt < 4; ++mt) {
        int r0 = m0 + m_w + mt * 16 + (lid >> 2);
#pragma unroll
        for (int nt = 0; nt < 4; ++nt) {
            int cN = n0 + n_w + nt * 8 + (lid & 3) * 2;
            if (cN < Nvalid) {
                float bx = 0.f, by = 0.f;
                if (bias) { bx = bias[cN]; by = bias[cN + 1]; }
                float a0 = acc[mt][nt][0] + bx, a1 = acc[mt][nt][1] + by;
                float a2 = acc[mt][nt][2] + bx, a3 = acc[mt][nt][3] + by;
                if (Add) {
                    const float* p0 = Add + (size_t)r0 * addStride + cN;
                    const float* p1 = Add + (size_t)(r0 + 8) * addStride + cN;
                    a0 += p0[0]; a1 += p0[1];
                    a2 += p1[0]; a3 += p1[1];
                }
                *(float2*)(C + (size_t)r0 * ldc + cN)       = make_float2(a0, a1);
                *(float2*)(C + (size_t)(r0 + 8) * ldc + cN) = make_float2(a2, a3);
            }
        }
    }
}

// ---------------- pointwise LSTM cell ----------------------------------------
__global__ void lstm_pointwise(const float* __restrict__ gates, long gstride,
                               bf16* __restrict__ hhi, bf16* __restrict__ hlo,
                               float* __restrict__ c,
                               bf16* __restrict__ h1hi, bf16* __restrict__ h1lo,
                               int t, int czero) {
    int idx = blockIdx.x * blockDim.x + threadIdx.x;
    if (idx >= B_SZ * H_SZ) return;
    int b = idx >> 8, j = idx & 255;
    const float* row = gates + (size_t)b * gstride;
    float iv = row[j], fv = row[256 + j], gv = row[512 + j], ov = row[768 + j];
    iv = 1.f / (1.f + expf(-iv));
    fv = 1.f / (1.f + expf(-fv));
    ov = 1.f / (1.f + expf(-ov));
    gv = tanhf(gv);
    float cold = czero ? 0.f : c[idx];
    float cn = fv * cold + iv * gv;
    float hn = ov * tanhf(cn);
    c[idx] = cn;
    bf16 hh = __float2bfloat16(hn);
    bf16 hl = __float2bfloat16(hn - __bfloat162float(hh));
    hhi[idx] = hh;
    hlo[idx] = hl;
    if (h1hi) {
        size_t o = ((size_t)b * T_SZ + t) * H_SZ + j;
        h1hi[o] = hh;
        h1lo[o] = hl;
    }
}

// ---------------- launch ------------------------------------------------------
extern "C" void kernel_launch(void* const* d_in, const int* in_sizes, int n_in,
                              void* d_out, int out_size)
{
    const int*   car    = (const int*)  d_in[0];
    const int*   reg    = (const int*)  d_in[1];
    const int*   poi    = (const int*)  d_in[2];
    const int*   week   = (const int*)  d_in[3];
    const int*   timei  = (const int*)  d_in[4];
    const float* car_e  = (const float*)d_in[5];
    const float* reg_e  = (const float*)d_in[6];
    const float* poi_e  = (const float*)d_in[7];
    const float* week_e = (const float*)d_in[8];
    const float* time_e = (const float*)d_in[9];
    const float* Wih0   = (const float*)d_in[10];
    const float* Whh0   = (const float*)d_in[11];
    const float* bih0   = (const float*)d_in[12];
    const float* bhh0   = (const float*)d_in[13];
    const float* Wih1   = (const float*)d_in[14];
    const float* Whh1   = (const float*)d_in[15];
    const float* bih1   = (const float*)d_in[16];
    const float* bhh1   = (const float*)d_in[17];
    const float* Wout   = (const float*)d_in[18];
    const float* bout   = (const float*)d_in[19];
    float* out = (float*)d_out;

    bf16 *xhi, *xlo, *h1hi, *h1lo, *hhi, *hlo;
    float *xg, *gates, *c, *bias0, *bias1;
    bf16 *wih0h, *wih0l, *whh0h, *whh0l, *wih1h, *wih1l, *whh1h, *whh1l, *wouth, *woutl;
    cudaGetSymbolAddress((void**)&xhi,   g_xhi);
    cudaGetSymbolAddress((void**)&xlo,   g_xlo);
    cudaGetSymbolAddress((void**)&xg,    g_xg);
    cudaGetSymbolAddress((void**)&h1hi,  g_h1hi);
    cudaGetSymbolAddress((void**)&h1lo,  g_h1lo);
    cudaGetSymbolAddress((void**)&gates, g_gates);
    cudaGetSymbolAddress((void**)&hhi,   g_hhi);
    cudaGetSymbolAddress((void**)&hlo,   g_hlo);
    cudaGetSymbolAddress((void**)&c,     g_c);
    cudaGetSymbolAddress((void**)&bias0, g_bias0);
    cudaGetSymbolAddress((void**)&bias1, g_bias1);
    cudaGetSymbolAddress((void**)&wih0h, g_wih0_hi); cudaGetSymbolAddress((void**)&wih0l, g_wih0_lo);
    cudaGetSymbolAddress((void**)&whh0h, g_whh0_hi); cudaGetSymbolAddress((void**)&whh0l, g_whh0_lo);
    cudaGetSymbolAddress((void**)&wih1h, g_wih1_hi); cudaGetSymbolAddress((void**)&wih1l, g_wih1_lo);
    cudaGetSymbolAddress((void**)&whh1h, g_whh1_hi); cudaGetSymbolAddress((void**)&whh1l, g_whh1_lo);
    cudaGetSymbolAddress((void**)&wouth, g_wout_hi); cudaGetSymbolAddress((void**)&woutl, g_wout_lo);

    cudaFuncSetAttribute(gemm_mma, cudaFuncAttributeMaxDynamicSharedMemorySize, SM_BYTES);

    const long XGSTRIDE = (long)T_SZ * G_SZ;

    prep_bias<<<(G_SZ + 255) / 256, 256>>>(bih0, bhh0, bih1, bhh1);
    {
        long t0 = 4L * 1 * 16384;
        prep_wsplit<<<(t0 + 255) / 256, 256>>>(Wih0, 39, 1024, 1, t0, wih0h, wih0l);
        long t1 = 4L * 4 * 16384;
        prep_wsplit<<<(t1 + 255) / 256, 256>>>(Whh0, 256, 1024, 4, t1, whh0h, whh0l);
        prep_wsplit<<<(t1 + 255) / 256, 256>>>(Wih1, 256, 1024, 4, t1, wih1h, wih1l);
        prep_wsplit<<<(t1 + 255) / 256, 256>>>(Whh1, 256, 1024, 4, t1, whh1h, whh1l);
        long t2 = 2L * 4 * 16384;
        prep_wsplit<<<(t2 + 255) / 256, 256>>>(Wout, 256, 500, 4, t2, wouth, woutl);
    }
    gather_kernel<<<((long)ROWS * XPAD + 255) / 256, 256>>>(
        car, reg, poi, week, timei, car_e, reg_e, poi_e, week_e, time_e);

    // layer0 input projection: xg = X @ Wih0^T + bias0
    gemm_mma<<<dim3(8, ROWS / 128), 256, SM_BYTES>>>(
        xhi, xlo, XPAD, wih0h, wih0l, 1, bias0, nullptr, 0, xg, G_SZ, G_SZ);

    // layer0 recurrence
    for (int t = 0; t < T_SZ; ++t) {
        const float* gsrc; long gstride;
        if (t == 0) { gsrc = xg; gstride = XGSTRIDE; }
        else {
            gemm_mma<<<dim3(8, B_SZ / 128), 256, SM_BYTES>>>(
                hhi, hlo, H_SZ, whh0h, whh0l, 4, nullptr, xg + (size_t)t * G_SZ, XGSTRIDE,
                gates, G_SZ, G_SZ);
            gsrc = gates; gstride = G_SZ;
        }
        lstm_pointwise<<<(B_SZ * H_SZ) / 256, 256>>>(gsrc, gstride, hhi, hlo, c, h1hi, h1lo, t, t == 0);
    }

    // layer1 input projection: xg = H1 @ Wih1^T + bias1
    gemm_mma<<<dim3(8, ROWS / 128), 256, SM_BYTES>>>(
        h1hi, h1lo, H_SZ, wih1h, wih1l, 4, bias1, nullptr, 0, xg, G_SZ, G_SZ);

    // layer1 recurrence
    for (int t = 0; t < T_SZ; ++t) {
        const float* gsrc; long gstride;
        if (t == 0) { gsrc = xg; gstride = XGSTRIDE; }
        else {
            gemm_mma<<<dim3(8, B_SZ / 128), 256, SM_BYTES>>>(
                hhi, hlo, H_SZ, whh1h, whh1l, 4, nullptr, xg + (size_t)t * G_SZ, XGSTRIDE,
                gates, G_SZ, G_SZ);
            gsrc = gates; gstride = G_SZ;
        }
        lstm_pointwise<<<(B_SZ * H_SZ) / 256, 256>>>(gsrc, gstride, hhi, hlo, c, nullptr, nullptr, t, t == 0);
    }

    // output head: out = h @ Wout^T + bout  (N padded to 512, valid 500)
    gemm_mma<<<dim3(4, B_SZ / 128), 256, SM_BYTES>>>(
        hhi, hlo, H_SZ, wouth, woutl, 4, bout, nullptr, 0, out, N_LABELS, N_LABELS);
}

// round 6
// speedup vs baseline: 2.3417x; 1.2017x over previous
#include <cuda_runtime.h>
#include <cuda_fp16.h>
#include <cstdint>
#include <math.h>

#define B_SZ     16384
#define T_SZ     10
#define H_SZ     256
#define G_SZ     1024
#define N_LABELS 500
#define ROWS     (B_SZ * T_SZ)     // 163840
#define XPAD     64
#define XGSTRIDE 10240             // T_SZ * G_SZ

typedef unsigned long long u64;
typedef unsigned int u32;
typedef __half fp16;

// ---------------- device scratch (no allocations allowed) --------------------
__device__ fp16  g_x   [(size_t)ROWS * XPAD];      // gathered input, fp16
__device__ float g_xg  [(size_t)ROWS * G_SZ];      // input projections (fp32, gate-permuted)
__device__ fp16  g_h1  [(size_t)ROWS * H_SZ];      // layer0 outputs, fp16
__device__ fp16  g_ha  [(size_t)B_SZ * H_SZ];      // h ping-pong buffers
__device__ fp16  g_hb  [(size_t)B_SZ * H_SZ];
__device__ float g_c   [(size_t)B_SZ * H_SZ];
__device__ float g_bias0[G_SZ];                    // permuted combined biases
__device__ float g_bias1[G_SZ];
// weight tile images (pre-split hi/lo fp16, pre-swizzled): [tile*nkc+kc][256][64]
__device__ fp16 g_wih0_hi[ 4 * 1 * 16384], g_wih0_lo[ 4 * 1 * 16384];
__device__ fp16 g_whh0_hi[ 4 * 4 * 16384], g_whh0_lo[ 4 * 4 * 16384];
__device__ fp16 g_wih1_hi[ 4 * 4 * 16384], g_wih1_lo[ 4 * 4 * 16384];
__device__ fp16 g_whh1_hi[ 4 * 4 * 16384], g_whh1_lo[ 4 * 4 * 16384];
__device__ fp16 g_wout_hi[ 2 * 4 * 16384], g_wout_lo[ 2 * 4 * 16384];

// ---------------- PTX helpers ------------------------------------------------
__device__ __forceinline__ u32 smem_u32(const void* p) {
    u32 a; asm("{ .reg .u64 t; cvta.to.shared.u64 t, %1; cvt.u32.u64 %0, t; }"
               : "=r"(a) : "l"(p));
    return a;
}
__device__ __forceinline__ void cp16(u32 dst, const void* src) {
    asm volatile("cp.async.cg.shared.global [%0], [%1], 16;" :: "r"(dst), "l"(src));
}
__device__ __forceinline__ void cp_commit() { asm volatile("cp.async.commit_group;"); }
template <int N> __device__ __forceinline__ void cp_wait() {
    asm volatile("cp.async.wait_group %0;" :: "n"(N));
}
__device__ __forceinline__ void ldm4(u32& r0, u32& r1, u32& r2, u32& r3, u32 addr) {
    asm volatile("ldmatrix.sync.aligned.m8n8.x4.shared.b16 {%0,%1,%2,%3}, [%4];"
                 : "=r"(r0), "=r"(r1), "=r"(r2), "=r"(r3) : "r"(addr));
}
__device__ __forceinline__ void mma16(float* d, const u32* a, const u32* b) {
    asm volatile("mma.sync.aligned.m16n8k16.row.col.f32.f16.f16.f32 "
                 "{%0,%1,%2,%3}, {%4,%5,%6,%7}, {%8,%9}, {%0,%1,%2,%3};"
                 : "+f"(d[0]), "+f"(d[1]), "+f"(d[2]), "+f"(d[3])
                 : "r"(a[0]), "r"(a[1]), "r"(a[2]), "r"(a[3]), "r"(b[0]), "r"(b[1]));
}

// ---------------- prep kernels ----------------------------------------------
// permuted combined biases: out index p = 4j+g  <-  n = g*256+j
__global__ void prep_bias(const float* bih0, const float* bhh0,
                          const float* bih1, const float* bhh1) {
    int p = blockIdx.x * blockDim.x + threadIdx.x;
    if (p < G_SZ) {
        int j = p >> 2, g = p & 3, n = g * 256 + j;
        g_bias0[p] = bih0[n] + bhh0[n];
        g_bias1[p] = bih1[n] + bhh1[n];
    }
}

// split W[Nrows,Kw] into hi/lo fp16 swizzled tile images; perm: gate interleave
__global__ void prep_wsplit(const float* __restrict__ W, int Kw, int Nrows,
                            int nkc, long total, int perm,
                            fp16* __restrict__ hi, fp16* __restrict__ lo) {
    long id = (long)blockIdx.x * blockDim.x + threadIdx.x;
    if (id >= total) return;
    int c  = (int)(id & 63);
    int r  = (int)((id >> 6) & 255);
    long tc = id >> 14;
    int kc = (int)(tc % nkc), nt = (int)(tc / nkc);
    int p = nt * 256 + r;
    int n = perm ? ((p & 3) * 256 + (p >> 2)) : p;
    int k = kc * 64 + c;
    float v = (n < Nrows && k < Kw) ? W[(size_t)n * Kw + k] : 0.f;
    fp16 h = __float2half(v);
    size_t pos = ((size_t)tc * 256 + r) * 64 + (size_t)((((c >> 3) ^ (r & 7)) << 3) | (c & 7));
    hi[pos] = h;
    lo[pos] = __float2half(v - __half2float(h));
}

// embedding gather -> fp16 X [ROWS, 64]
__global__ void gather_kernel(const int* __restrict__ car, const int* __restrict__ reg,
                              const int* __restrict__ poi, const int* __restrict__ week,
                              const int* __restrict__ timei,
                              const float* __restrict__ ce, const float* __restrict__ re,
                              const float* __restrict__ pe, const float* __restrict__ we,
                              const float* __restrict__ te) {
    long i = (long)blockIdx.x * blockDim.x + threadIdx.x;
    if (i >= (long)ROWS * XPAD) return;
    long r = i / XPAD; int j = (int)(i % XPAD);
    float v = 0.f;
    if      (j < 16) v = ce[(size_t)car  [r] * 16 + j];
    else if (j < 24) v = re[(size_t)reg  [r] * 8  + (j - 16)];
    else if (j < 28) v = pe[(size_t)poi  [r] * 4  + (j - 24)];
    else if (j < 31) v = we[(size_t)week [r] * 3  + (j - 28)];
    else if (j < 39) v = te[(size_t)timei[r] * 8  + (j - 31)];
    g_x[i] = __float2half(v);
}

// ---------------- shared GEMM mainloop pieces --------------------------------
// BM=128, BN=128, BK=64; 256 thr, 8 warps 2x4 (warp tile 64x32);
// 2 passes per k16: A*Whi + A*Wlo.  Stage = A 16KB | Whi 16KB | Wlo 16KB.
#define STG_BYTES 49152
#define SM_BYTES  (2 * STG_BYTES)   // 98304

#define GEMM_MAINLOOP(A_, lda_, Whi_, Wlo_, nkc_, m0_, tile_, rowbase_)                \
    const int au = tid & 7, ar = tid >> 3;                                             \
    auto load_stage = [&](int s, int kc) {                                             \
        u32 base = sb + s * STG_BYTES;                                                 \
        const size_t acol = (size_t)kc * 64 + au * 8;                                  \
        _Pragma("unroll")                                                              \
        for (int i = 0; i < 4; i++) {                                                  \
            int r = ar + i * 32;                                                       \
            u32 d = base + ((r * 64 + ((au ^ (r & 7)) << 3)) << 1);                    \
            cp16(d, A_ + (size_t)(m0_ + r) * lda_ + acol);                             \
        }                                                                              \
        const size_t ib = (size_t)(tile_ * nkc_ + kc) * 16384 + (size_t)rowbase_ * 64; \
        _Pragma("unroll")                                                              \
        for (int i = 0; i < 4; i++) {                                                  \
            int j = tid + i * 256;                                                     \
            cp16(base + 16384 + j * 16, Whi_ + ib + (size_t)j * 8);                    \
            cp16(base + 32768 + j * 16, Wlo_ + ib + (size_t)j * 8);                    \
        }                                                                              \
        cp_commit();                                                                   \
    };                                                                                 \
    const int lrow = lid & 15, lk = lid >> 4;                                          \
    load_stage(0, 0);                                                                  \
    for (int kc = 0; kc < nkc_; ++kc) {                                                \
        if (kc + 1 < nkc_) { load_stage((kc + 1) & 1, kc + 1); cp_wait<1>(); }         \
        else              { cp_wait<0>(); }                                            \
        __syncthreads();                                                               \
        const u32 aBase = sb + (kc & 1) * STG_BYTES;                                   \
        const u32 bBase = aBase + 16384;                                               \
        _Pragma("unroll")                                                              \
        for (int k16 = 0; k16 < 4; ++k16) {                                            \
            const int kb8 = k16 * 2 + lk;                                              \
            u32 bh[4][2], bl[4][2];                                                    \
            _Pragma("unroll")                                                          \
            for (int blk = 0; blk < 2; ++blk) {                                        \
                int row = n_w + blk * 16 + lrow;                                       \
                u32 ad = bBase + ((row * 64 + ((kb8 ^ (row & 7)) << 3)) << 1);         \
                u32 r0, r1, r2, r3;                                                    \
                ldm4(r0, r1, r2, r3, ad);                                              \
                bh[blk * 2][0] = r0; bh[blk * 2][1] = r2;                              \
                bh[blk * 2 + 1][0] = r1; bh[blk * 2 + 1][1] = r3;                      \
                ldm4(r0, r1, r2, r3, ad + 16384);                                      \
                bl[blk * 2][0] = r0; bl[blk * 2][1] = r2;                              \
                bl[blk * 2 + 1][0] = r1; bl[blk * 2 + 1][1] = r3;                      \
            }                                                                          \
            _Pragma("unroll")                                                          \
            for (int mt = 0; mt < 4; ++mt) {                                           \
                int row = m_w + mt * 16 + lrow;                                        \
                u32 ad = aBase + ((row * 64 + ((kb8 ^ (row & 7)) << 3)) << 1);         \
                u32 af[4];                                                             \
                ldm4(af[0], af[1], af[2], af[3], ad);                                  \
                _Pragma("unroll")                                                      \
                for (int nt = 0; nt < 4; ++nt) mma16(acc[mt][nt], af, bh[nt]);         \
                _Pragma("unroll")                                                      \
                for (int nt = 0; nt < 4; ++nt) mma16(acc[mt][nt], af, bl[nt]);         \
            }                                                                          \
        }                                                                              \
        __syncthreads();                                                               \
    }

// ---------------- generic GEMM (xg projections, head) ------------------------
__global__ void __launch_bounds__(256)
gemm_mma(const fp16* __restrict__ A, int lda,
         const fp16* __restrict__ Whi, const fp16* __restrict__ Wlo, int nkc,
         const float* __restrict__ bias,
         float* __restrict__ C, int ldc, int Nvalid)
{
    extern __shared__ __align__(1024) char sm[];
    const u32 sb = smem_u32(sm);
    const int tid = threadIdx.x, wid = tid >> 5, lid = tid & 31;
    const int m0 = blockIdx.y * 128;
    const int n0 = blockIdx.x * 128;
    const int tile = n0 >> 8, rowbase = n0 & 255;
    const int m_w = (wid >> 2) * 64, n_w = (wid & 2 ? 64 : 0) + (wid & 1) * 32;

    float acc[4][4][4];
#pragma unroll
    for (int a = 0; a < 4; a++)
#pragma unroll
        for (int b = 0; b < 4; b++)
#pragma unroll
            for (int e = 0; e < 4; e++) acc[a][b][e] = 0.f;

    GEMM_MAINLOOP(A, lda, Whi, Wlo, nkc, m0, tile, rowbase)

#pragma unroll
    for (int mt = 0; mt < 4; ++mt) {
        int r0 = m0 + m_w + mt * 16 + (lid >> 2);
#pragma unroll
        for (int nt = 0; nt < 4; ++nt) {
            int cN = n0 + n_w + nt * 8 + (lid & 3) * 2;
            if (cN < Nvalid) {
                float bx = bias[cN], by = bias[cN + 1];
                *(float2*)(C + (size_t)r0 * ldc + cN) =
                    make_float2(acc[mt][nt][0] + bx, acc[mt][nt][1] + by);
                *(float2*)(C + (size_t)(r0 + 8) * ldc + cN) =
                    make_float2(acc[mt][nt][2] + bx, acc[mt][nt][3] + by);
            }
        }
    }
}

// ---------------- recurrent GEMM with fused LSTM cell epilogue ----------------
// N=1024 (gate-permuted p=4j+g), M=B_SZ, K=256 (nkc=4).
__global__ void __launch_bounds__(256)
gemm_rec(const fp16* __restrict__ A,
         const fp16* __restrict__ Whi, const fp16* __restrict__ Wlo,
         const float* __restrict__ xg, int t,
         float* __restrict__ c, fp16* __restrict__ hout, fp16* __restrict__ h1out)
{
    extern __shared__ __align__(1024) char sm[];
    const u32 sb = smem_u32(sm);
    const int tid = threadIdx.x, wid = tid >> 5, lid = tid & 31;
    const int m0 = blockIdx.y * 128;
    const int n0 = blockIdx.x * 128;
    const int tile = n0 >> 8, rowbase = n0 & 255;
    const int m_w = (wid >> 2) * 64, n_w = (wid & 2 ? 64 : 0) + (wid & 1) * 32;
    const int nkc = 4, lda = H_SZ;

    float acc[4][4][4];
#pragma unroll
    for (int a = 0; a < 4; a++)
#pragma unroll
        for (int b = 0; b < 4; b++)
#pragma unroll
            for (int e = 0; e < 4; e++) acc[a][b][e] = 0.f;

    GEMM_MAINLOOP(A, lda, Whi, Wlo, nkc, m0, tile, rowbase)

    // fused cell epilogue: exchange half-quadruples between lane pairs
    const int odd = lid & 1;
#pragma unroll
    for (int mt = 0; mt < 4; ++mt) {
        int r0 = m0 + m_w + mt * 16 + (lid >> 2);
#pragma unroll
        for (int nt = 0; nt < 4; ++nt) {
            float* a4 = acc[mt][nt];
            int p = n0 + n_w + nt * 8 + (lid & 3) * 2;
            int j = p >> 2;
            float s0 = odd ? a4[0] : a4[2];
            float s1 = odd ? a4[1] : a4[3];
            float r0v = __shfl_xor_sync(0xFFFFFFFFu, s0, 1);
            float r1v = __shfl_xor_sync(0xFFFFFFFFu, s1, 1);
            float gi, gf, gg, go;
            int row;
            if (odd) { gi = r0v;  gf = r1v;  gg = a4[2]; go = a4[3]; row = r0 + 8; }
            else     { gi = a4[0]; gf = a4[1]; gg = r0v; go = r1v;  row = r0; }
            float4 xv = *(const float4*)(xg + (size_t)row * XGSTRIDE + (size_t)t * G_SZ + 4 * j);
            gi += xv.x; gf += xv.y; gg += xv.z; go += xv.w;
            gi = 1.f / (1.f + expf(-gi));
            gf = 1.f / (1.f + expf(-gf));
            go = 1.f / (1.f + expf(-go));
            gg = tanhf(gg);
            size_t ci = (size_t)row * H_SZ + j;
            float cn = gf * c[ci] + gi * gg;
            float hn = go * tanhf(cn);
            c[ci] = cn;
            hout[ci] = __float2half(hn);
            if (h1out) h1out[((size_t)row * T_SZ + t) * H_SZ + j] = __float2half(hn);
        }
    }
}

// ---------------- t=0 cell (no GEMM; gates = xg, c_old = 0) -------------------
__global__ void cell_t0(const float* __restrict__ xg,
                        float* __restrict__ c, fp16* __restrict__ hout,
                        fp16* __restrict__ h1out) {
    int idx = blockIdx.x * blockDim.x + threadIdx.x;
    if (idx >= B_SZ * H_SZ) return;
    int b = idx >> 8, j = idx & 255;
    float4 xv = *(const float4*)(xg + (size_t)b * XGSTRIDE + 4 * j);
    float gi = 1.f / (1.f + expf(-xv.x));
    float gf = 1.f / (1.f + expf(-xv.y));
    float gg = tanhf(xv.z);
    float go = 1.f / (1.f + expf(-xv.w));
    float cn = gi * gg;
    float hn = go * tanhf(cn);
    c[idx] = cn;
    hout[idx] = __float2half(hn);
    if (h1out) h1out[(size_t)b * T_SZ * H_SZ + j] = __float2half(hn);
}

// ---------------- launch ------------------------------------------------------
extern "C" void kernel_launch(void* const* d_in, const int* in_sizes, int n_in,
                              void* d_out, int out_size)
{
    const int*   car    = (const int*)  d_in[0];
    const int*   reg    = (const int*)  d_in[1];
    const int*   poi    = (const int*)  d_in[2];
    const int*   week   = (const int*)  d_in[3];
    const int*   timei  = (const int*)  d_in[4];
    const float* car_e  = (const float*)d_in[5];
    const float* reg_e  = (const float*)d_in[6];
    const float* poi_e  = (const float*)d_in[7];
    const float* week_e = (const float*)d_in[8];
    const float* time_e = (const float*)d_in[9];
    const float* Wih0   = (const float*)d_in[10];
    const float* Whh0   = (const float*)d_in[11];
    const float* bih0   = (const float*)d_in[12];
    const float* bhh0   = (const float*)d_in[13];
    const float* Wih1   = (const float*)d_in[14];
    const float* Whh1   = (const float*)d_in[15];
    const float* bih1   = (const float*)d_in[16];
    const float* bhh1   = (const float*)d_in[17];
    const float* Wout   = (const float*)d_in[18];
    const float* bout   = (const float*)d_in[19];
    float* out = (float*)d_out;

    fp16 *x, *h1, *ha, *hb;
    float *xg, *c, *bias0, *bias1;
    fp16 *wih0h, *wih0l, *whh0h, *whh0l, *wih1h, *wih1l, *whh1h, *whh1l, *wouth, *woutl;
    cudaGetSymbolAddress((void**)&x,     g_x);
    cudaGetSymbolAddress((void**)&xg,    g_xg);
    cudaGetSymbolAddress((void**)&h1,    g_h1);
    cudaGetSymbolAddress((void**)&ha,    g_ha);
    cudaGetSymbolAddress((void**)&hb,    g_hb);
    cudaGetSymbolAddress((void**)&c,     g_c);
    cudaGetSymbolAddress((void**)&bias0, g_bias0);
    cudaGetSymbolAddress((void**)&bias1, g_bias1);
    cudaGetSymbolAddress((void**)&wih0h, g_wih0_hi); cudaGetSymbolAddress((void**)&wih0l, g_wih0_lo);
    cudaGetSymbolAddress((void**)&whh0h, g_whh0_hi); cudaGetSymbolAddress((void**)&whh0l, g_whh0_lo);
    cudaGetSymbolAddress((void**)&wih1h, g_wih1_hi); cudaGetSymbolAddress((void**)&wih1l, g_wih1_lo);
    cudaGetSymbolAddress((void**)&whh1h, g_whh1_hi); cudaGetSymbolAddress((void**)&whh1l, g_whh1_lo);
    cudaGetSymbolAddress((void**)&wouth, g_wout_hi); cudaGetSymbolAddress((void**)&woutl, g_wout_lo);

    cudaFuncSetAttribute(gemm_mma, cudaFuncAttributeMaxDynamicSharedMemorySize, SM_BYTES);
    cudaFuncSetAttribute(gemm_rec, cudaFuncAttributeMaxDynamicSharedMemorySize, SM_BYTES);

    fp16* hbuf[2] = { ha, hb };

    prep_bias<<<(G_SZ + 255) / 256, 256>>>(bih0, bhh0, bih1, bhh1);
    {
        long t0 = 4L * 1 * 16384;
        prep_wsplit<<<(t0 + 255) / 256, 256>>>(Wih0, 39, 1024, 1, t0, 1, wih0h, wih0l);
        long t1 = 4L * 4 * 16384;
        prep_wsplit<<<(t1 + 255) / 256, 256>>>(Whh0, 256, 1024, 4, t1, 1, whh0h, whh0l);
        prep_wsplit<<<(t1 + 255) / 256, 256>>>(Wih1, 256, 1024, 4, t1, 1, wih1h, wih1l);
        prep_wsplit<<<(t1 + 255) / 256, 256>>>(Whh1, 256, 1024, 4, t1, 1, whh1h, whh1l);
        long t2 = 2L * 4 * 16384;
        prep_wsplit<<<(t2 + 255) / 256, 256>>>(Wout, 256, 500, 4, t2, 0, wouth, woutl);
    }
    gather_kernel<<<((long)ROWS * XPAD + 255) / 256, 256>>>(
        car, reg, poi, week, timei, car_e, reg_e, poi_e, week_e, time_e);

    // layer0 input projection: xg = X @ Wih0p^T + bias0 (gate-permuted)
    gemm_mma<<<dim3(8, ROWS / 128), 256, SM_BYTES>>>(
        x, XPAD, wih0h, wih0l, 1, bias0, xg, G_SZ, G_SZ);

    // layer0 recurrence (cell fused into GEMM epilogue)
    cell_t0<<<(B_SZ * H_SZ) / 256, 256>>>(xg, c, hbuf[0], h1);
    for (int t = 1; t < T_SZ; ++t)
        gemm_rec<<<dim3(8, B_SZ / 128), 256, SM_BYTES>>>(
            hbuf[(t - 1) & 1], whh0h, whh0l, xg, t, c, hbuf[t & 1], h1);

    // layer1 input projection: xg = H1 @ Wih1^T + bias1 (gate-permuted)
    gemm_mma<<<dim3(8, ROWS / 128), 256, SM_BYTES>>>(
        h1, H_SZ, wih1h, wih1l, 4, bias1, xg, G_SZ, G_SZ);

    // layer1 recurrence
    cell_t0<<<(B_SZ * H_SZ) / 256, 256>>>(xg, c, hbuf[0], nullptr);
    for (int t = 1; t < T_SZ; ++t)
        gemm_rec<<<dim3(8, B_SZ / 128), 256, SM_BYTES>>>(
            hbuf[(t - 1) & 1], whh1h, whh1l, xg, t, c, hbuf[t & 1], nullptr);

    // output head: out = h_last @ Wout^T + bout (N padded 512, valid 500)
    gemm_mma<<<dim3(4, B_SZ / 128), 256, SM_BYTES>>>(
        hbuf[1], H_SZ, wouth, woutl, 4, bout, out, N_LABELS, N_LABELS);
}